// round 7
// baseline (speedup 1.0000x reference)
#include <cuda_runtime.h>
#include <cuda_fp16.h>
#include <cuda_bf16.h>
#include <cstdint>

#define BB 4
#define NN 8192
#define KK 16
#define DD 128
#define GG 32
#define MM (BB*NN)          // 32768 rows
#define BN_EPS 1e-5f

#define NPART 4096          // gather blocks = stats partials

// ---------------- scratch (device globals; no allocation) ----------------
__device__ __half g_h[(size_t)MM * DD];          // projected features, fp16, 8 MB
__device__ __nv_bfloat16 g_whi[DD * DD];         // W split hi
__device__ __nv_bfloat16 g_wlo[DD * DD];         // W split lo
__device__ float g_psum [NPART][DD];             // per-gather-block partial sums
__device__ float g_psum2[NPART][DD];             // per-gather-block partial sumsq
__device__ float g_scale[DD];                    // fused BN scale
__device__ float g_shift[DD];                    // fused BN shift

// ---------------- kernel 0: split W into bf16 hi/lo (runs once, tiny) -----
__global__ void __launch_bounds__(256) wprep_kernel(const float* __restrict__ W) {
    for (int i = threadIdx.x; i < DD * DD; i += 256) {
        const float v = W[i];
        const __nv_bfloat16 hi = __float2bfloat16(v);
        g_whi[i] = hi;
        g_wlo[i] = __float2bfloat16(v - __bfloat162float(hi));
    }
}

// ---------------- mma / ldmatrix helpers ----------------------------------
#define LDSM4(r0, r1, r2, r3, addr)                                            \
    asm volatile("ldmatrix.sync.aligned.m8n8.x4.shared.b16 {%0,%1,%2,%3}, [%4];" \
                 : "=r"(r0), "=r"(r1), "=r"(r2), "=r"(r3) : "r"(addr))

__device__ __forceinline__ void mma_bf16(float c[4],
                                         uint32_t a0, uint32_t a1, uint32_t a2, uint32_t a3,
                                         uint32_t b0, uint32_t b1) {
    asm volatile(
        "mma.sync.aligned.m16n8k16.row.col.f32.bf16.bf16.f32 "
        "{%0,%1,%2,%3}, {%4,%5,%6,%7}, {%8,%9}, {%0,%1,%2,%3};"
        : "+f"(c[0]), "+f"(c[1]), "+f"(c[2]), "+f"(c[3])
        : "r"(a0), "r"(a1), "r"(a2), "r"(a3), "r"(b0), "r"(b1));
}

// ---------------- kernel 1: H = X * W^T, split-bf16 3-MMA -----------------
// Block 256 thr (8 warps: wm 0..3, wn 0..1). Tile M128 x N128, warp 32x64.
// K staged by 32. W pre-split (global bf16); X split in-kernel. Occupancy 2.
// Epilogue staged through smem for coalesced uint4 stores.
#define BK 32
#define RS 40      // smem row stride, bf16 elems (80 B -> LDSM conflict-free)
#define ORS 136    // epilogue smem row stride, halfs (272 B -> STS conflict-free)
__global__ void __launch_bounds__(256, 2) gemm_kernel(const float* __restrict__ X,
                                                      __half* __restrict__ H) {
    __shared__ __align__(16) char smem_raw[4 * 128 * RS * 2];   // 40960 B
    __nv_bfloat16* Xhi = (__nv_bfloat16*)smem_raw;
    __nv_bfloat16* Xlo = Xhi + 128 * RS;
    __nv_bfloat16* Whi = Xlo + 128 * RS;
    __nv_bfloat16* Wlo = Whi + 128 * RS;
    __half* Outs = (__half*)smem_raw;                           // reused after MMA

    const int tid  = threadIdx.x;
    const int warp = tid >> 5;
    const int lane = tid & 31;
    const int wm   = warp >> 1;
    const int wn   = warp & 1;
    const int m0   = blockIdx.x * 128;
    const int gr   = lane >> 2;
    const int gc   = lane & 3;
    const int l16  = lane & 15;
    const int kh   = (lane >> 4) << 3;

    float c[2][8][4];
#pragma unroll
    for (int i = 0; i < 2; i++)
#pragma unroll
        for (int j = 0; j < 8; j++)
#pragma unroll
            for (int t = 0; t < 4; t++) c[i][j][t] = 0.f;

    const uint32_t xhi_b = (uint32_t)__cvta_generic_to_shared(Xhi);
    const uint32_t xlo_b = (uint32_t)__cvta_generic_to_shared(Xlo);
    const uint32_t whi_b = (uint32_t)__cvta_generic_to_shared(Whi);
    const uint32_t wlo_b = (uint32_t)__cvta_generic_to_shared(Wlo);

    for (int kcs = 0; kcs < DD / BK; kcs++) {
        const int kc = kcs * BK;
#pragma unroll
        for (int i = 0; i < 4; i++) {
            const int q   = tid + i * 256;   // 0..1023
            const int row = q >> 3;          // 0..127
            const int cq  = q & 7;           // 4-elem group within 32 k's
            // X: fp32 load + split
            {
                const float4 v = *(const float4*)(X + (size_t)(m0 + row) * DD + kc + cq * 4);
                __nv_bfloat16 hx = __float2bfloat16(v.x);
                __nv_bfloat16 hy = __float2bfloat16(v.y);
                __nv_bfloat16 hz = __float2bfloat16(v.z);
                __nv_bfloat16 hw = __float2bfloat16(v.w);
                __nv_bfloat162 hp0 = __halves2bfloat162(hx, hy);
                __nv_bfloat162 hp1 = __halves2bfloat162(hz, hw);
                __nv_bfloat162 lp0 = __halves2bfloat162(
                    __float2bfloat16(v.x - __bfloat162float(hx)),
                    __float2bfloat16(v.y - __bfloat162float(hy)));
                __nv_bfloat162 lp1 = __halves2bfloat162(
                    __float2bfloat16(v.z - __bfloat162float(hz)),
                    __float2bfloat16(v.w - __bfloat162float(hw)));
                *(uint2*)&Xhi[row * RS + cq * 4] =
                    make_uint2(*(uint32_t*)&hp0, *(uint32_t*)&hp1);
                *(uint2*)&Xlo[row * RS + cq * 4] =
                    make_uint2(*(uint32_t*)&lp0, *(uint32_t*)&lp1);
            }
            // W: pre-split bf16, straight copy
            {
                const uint2 hv = *(const uint2*)(g_whi + (size_t)row * DD + kc + cq * 4);
                const uint2 lv = *(const uint2*)(g_wlo + (size_t)row * DD + kc + cq * 4);
                *(uint2*)&Whi[row * RS + cq * 4] = hv;
                *(uint2*)&Wlo[row * RS + cq * 4] = lv;
            }
        }
        __syncthreads();

#pragma unroll
        for (int s = 0; s < BK / 16; s++) {
            const uint32_t koff = (kh + s * 16) * 2;

            uint32_t ahi[2][4], alo[2][4];
#pragma unroll
            for (int am = 0; am < 2; am++) {
                const uint32_t ro = (uint32_t)(wm * 32 + am * 16 + l16) * (RS * 2) + koff;
                LDSM4(ahi[am][0], ahi[am][1], ahi[am][2], ahi[am][3], xhi_b + ro);
                LDSM4(alo[am][0], alo[am][1], alo[am][2], alo[am][3], xlo_b + ro);
            }
            uint32_t bhi[4][4], blo[4][4];
#pragma unroll
            for (int p = 0; p < 4; p++) {
                const uint32_t ro = (uint32_t)(wn * 64 + p * 16 + l16) * (RS * 2) + koff;
                LDSM4(bhi[p][0], bhi[p][1], bhi[p][2], bhi[p][3], whi_b + ro);
                LDSM4(blo[p][0], blo[p][1], blo[p][2], blo[p][3], wlo_b + ro);
            }

#pragma unroll
            for (int p = 0; p < 4; p++)
#pragma unroll
                for (int e = 0; e < 2; e++) {
                    const int an = 2 * p + e;
                    const uint32_t bh0 = bhi[p][e], bh1 = bhi[p][2 + e];
                    const uint32_t bl0 = blo[p][e], bl1 = blo[p][2 + e];
#pragma unroll
                    for (int am = 0; am < 2; am++) {
                        mma_bf16(c[am][an], ahi[am][0], ahi[am][1], ahi[am][2], ahi[am][3], bh0, bh1);
                        mma_bf16(c[am][an], ahi[am][0], ahi[am][1], ahi[am][2], ahi[am][3], bl0, bl1);
                        mma_bf16(c[am][an], alo[am][0], alo[am][1], alo[am][2], alo[am][3], bh0, bh1);
                    }
                }
        }
        __syncthreads();
    }

    // epilogue: accums -> smem fp16 tile (conflict-free stride) -> coalesced STG
#pragma unroll
    for (int am = 0; am < 2; am++) {
        const int r0 = wm * 32 + am * 16 + gr;
#pragma unroll
        for (int an = 0; an < 8; an++) {
            const int col = wn * 64 + an * 8 + 2 * gc;
            *(__half2*)&Outs[r0 * ORS + col] =
                __floats2half2_rn(c[am][an][0], c[am][an][1]);
            *(__half2*)&Outs[(r0 + 8) * ORS + col] =
                __floats2half2_rn(c[am][an][2], c[am][an][3]);
        }
    }
    __syncthreads();
#pragma unroll
    for (int j = 0; j < 8; j++) {
        const int idx = tid + j * 256;       // 0..2047 uint4 slots
        const int row = idx >> 4;            // 16 uint4 per row
        const int cg  = (idx & 15) * 8;      // col (halfs)
        *(uint4*)(H + (size_t)(m0 + row) * DD + cg) =
            *(const uint4*)&Outs[row * ORS + cg];
    }
}

// ---------------- kernel 2: gather + encoding + max + stats partials ------
// One warp per point, 8 points/block. Lane g owns channels [4g,4g+4).
__global__ void __launch_bounds__(256) gather_kernel(const __half* __restrict__ H,
                                                     const float* __restrict__ xyz,
                                                     const int* __restrict__ knn,
                                                     const float* __restrict__ coor,
                                                     const float* __restrict__ scale,
                                                     float* __restrict__ agg) {
    __shared__ float sh_s[8][132];
    __shared__ float sh_q[8][132];

    const int warp = (blockIdx.x * blockDim.x + threadIdx.x) >> 5;
    const int wloc = threadIdx.x >> 5;
    const int lane = threadIdx.x & 31;

    const int b = warp >> 13;          // warp / 8192
    const int base = b << 13;          // b*N

    const float wx = coor[3 * lane + 0];
    const float wy = coor[3 * lane + 1];
    const float wz = coor[3 * lane + 2];
    const float sv = scale[lane];
    const float ws = sv * sv;

    const float* cptr = xyz + (size_t)warp * 3;
    const float cx = cptr[0], cy = cptr[1], cz = cptr[2];

    const int nb = knn[(size_t)warp * KK + (lane & 15)];

    float4 acc = make_float4(-3.402823466e38f, -3.402823466e38f,
                             -3.402823466e38f, -3.402823466e38f);

#pragma unroll
    for (int k = 0; k < KK; k++) {
        const int idx = __shfl_sync(0xffffffffu, nb, k);
        const int row = base + idx;
        const float* nx = xyz + (size_t)row * 3;
        const float rx = nx[0] - cx;
        const float ry = nx[1] - cy;
        const float rz = nx[2] - cz;
        const float r2 = fmaf(rx, rx, fmaf(ry, ry, rz * rz));
        const float e  = fmaf(rx, wx, fmaf(ry, wy, fmaf(rz, wz, r2 * ws)));
        const uint2 hv = *(const uint2*)(H + (size_t)row * DD + lane * 4);
        const float2 f0 = __half22float2(*(const __half2*)&hv.x);
        const float2 f1 = __half22float2(*(const __half2*)&hv.y);
        acc.x = fmaxf(acc.x, f0.x + e);
        acc.y = fmaxf(acc.y, f0.y + e);
        acc.z = fmaxf(acc.z, f1.x + e);
        acc.w = fmaxf(acc.w, f1.y + e);
    }

    *(float4*)(agg + (size_t)warp * DD + lane * 4) = acc;

    sh_s[wloc][lane * 4 + 0] = acc.x;
    sh_s[wloc][lane * 4 + 1] = acc.y;
    sh_s[wloc][lane * 4 + 2] = acc.z;
    sh_s[wloc][lane * 4 + 3] = acc.w;
    sh_q[wloc][lane * 4 + 0] = acc.x * acc.x;
    sh_q[wloc][lane * 4 + 1] = acc.y * acc.y;
    sh_q[wloc][lane * 4 + 2] = acc.z * acc.z;
    sh_q[wloc][lane * 4 + 3] = acc.w * acc.w;
    __syncthreads();

    if (threadIdx.x < 128) {
        const int ch = threadIdx.x;
        float s = 0.f;
#pragma unroll
        for (int w = 0; w < 8; w++) s += sh_s[w][ch];
        g_psum[blockIdx.x][ch] = s;
    } else {
        const int ch = threadIdx.x - 128;
        float q = 0.f;
#pragma unroll
        for (int w = 0; w < 8; w++) q += sh_q[w][ch];
        g_psum2[blockIdx.x][ch] = q;
    }
}

// ---------------- kernel 3: stats finalize (one block per channel) --------
__global__ void __launch_bounds__(256) stats2_kernel(const float* __restrict__ bn_w,
                                                     const float* __restrict__ bn_b) {
    __shared__ float rs[256], rq[256];
    const int ch  = blockIdx.x;
    const int tid = threadIdx.x;

    float s = 0.f, q = 0.f;
    for (int p = tid; p < NPART; p += 256) {
        s += g_psum[p][ch];
        q += g_psum2[p][ch];
    }
    rs[tid] = s;
    rq[tid] = q;
    __syncthreads();
#pragma unroll
    for (int st = 128; st > 0; st >>= 1) {
        if (tid < st) {
            rs[tid] += rs[tid + st];
            rq[tid] += rq[tid + st];
        }
        __syncthreads();
    }
    if (tid == 0) {
        const float inv_m = 1.f / (float)MM;
        const float mean = rs[0] * inv_m;
        const float var  = fmaf(-mean, mean, rq[0] * inv_m);
        const float a = bn_w[ch] * rsqrtf(var + BN_EPS);
        g_scale[ch] = a;
        g_shift[ch] = fmaf(-mean, a, bn_b[ch]);
    }
}

// ---------------- kernel 4: in-place normalize (register LUT) -------------
__global__ void __launch_bounds__(256) norm_kernel(float* __restrict__ out) {
    const int t0 = blockIdx.x * blockDim.x + threadIdx.x;
    const int c0 = (t0 & 31) * 4;
    const float s0 = g_scale[c0 + 0], s1 = g_scale[c0 + 1];
    const float s2 = g_scale[c0 + 2], s3 = g_scale[c0 + 3];
    const float b0 = g_shift[c0 + 0], b1 = g_shift[c0 + 1];
    const float b2 = g_shift[c0 + 2], b3 = g_shift[c0 + 3];

    const int total  = MM * (DD / 4);
    const int stride = gridDim.x * blockDim.x;   // multiple of 32

    for (int t = t0; t < total; t += stride) {
        float4 v = __ldcs((const float4*)out + t);
        v.x = fmaf(v.x, s0, b0);
        v.y = fmaf(v.y, s1, b1);
        v.z = fmaf(v.z, s2, b2);
        v.w = fmaf(v.w, s3, b3);
        __stcs((float4*)out + t, v);
    }
}

// ---------------- launch ---------------------------------------------------
extern "C" void kernel_launch(void* const* d_in, const int* in_sizes, int n_in,
                              void* d_out, int out_size) {
    const float* x      = (const float*)d_in[0];
    const float* xyz    = (const float*)d_in[1];
    const int*   knn    = (const int*)  d_in[2];
    const float* proj_w = (const float*)d_in[3];
    const float* coor   = (const float*)d_in[4];
    const float* scale  = (const float*)d_in[5];
    const float* bn_w   = (const float*)d_in[6];
    const float* bn_b   = (const float*)d_in[7];
    float* out = (float*)d_out;

    __half* h;
    cudaGetSymbolAddress((void**)&h, g_h);

    wprep_kernel<<<1, 256>>>(proj_w);
    gemm_kernel<<<MM / 128, 256>>>(x, h);
    gather_kernel<<<MM / 8, 256>>>(h, xyz, knn, coor, scale, out);
    stats2_kernel<<<DD, 256>>>(bn_w, bn_b);
    norm_kernel<<<1024, 256>>>(out);
}

// round 8
// speedup vs baseline: 1.1177x; 1.1177x over previous
#include <cuda_runtime.h>
#include <cuda_fp16.h>
#include <cuda_bf16.h>
#include <cstdint>

#define BB 4
#define NN 8192
#define KK 16
#define DD 128
#define GG 32
#define MM (BB*NN)          // 32768 rows
#define BN_EPS 1e-5f

#define NPART 4096          // gather blocks = stats partials
#define NMID 128            // stage-A output rows

// ---------------- scratch (device globals; no allocation) ----------------
__device__ __half g_h[(size_t)MM * DD];       // projected features, fp16, 8 MB
__device__ float g_psum [NPART][DD];          // per-gather-block partial sums
__device__ float g_psum2[NPART][DD];          // per-gather-block partial sumsq
__device__ float g_mid  [NMID][DD];           // stage-A sums
__device__ float g_mid2 [NMID][DD];           // stage-A sumsq
__device__ float g_scale[DD];                 // fused BN scale
__device__ float g_shift[DD];                 // fused BN shift

// ---------------- mma / ldmatrix helpers ----------------------------------
#define LDSM4(r0, r1, r2, r3, addr)                                            \
    asm volatile("ldmatrix.sync.aligned.m8n8.x4.shared.b16 {%0,%1,%2,%3}, [%4];" \
                 : "=r"(r0), "=r"(r1), "=r"(r2), "=r"(r3) : "r"(addr))

__device__ __forceinline__ void mma_bf16(float c[4],
                                         uint32_t a0, uint32_t a1, uint32_t a2, uint32_t a3,
                                         uint32_t b0, uint32_t b1) {
    asm volatile(
        "mma.sync.aligned.m16n8k16.row.col.f32.bf16.bf16.f32 "
        "{%0,%1,%2,%3}, {%4,%5,%6,%7}, {%8,%9}, {%0,%1,%2,%3};"
        : "+f"(c[0]), "+f"(c[1]), "+f"(c[2]), "+f"(c[3])
        : "r"(a0), "r"(a1), "r"(a2), "r"(a3), "r"(b0), "r"(b1));
}

// ---------------- kernel 1: H = X * W^T, split-bf16 3-MMA (R4 form) -------
#define BK 32
#define RS 40   // smem row stride in bf16 elems (80 B -> LDSM conflict-free)
__global__ void __launch_bounds__(256) gemm_kernel(const float* __restrict__ X,
                                                   const float* __restrict__ W,
                                                   __half* __restrict__ H) {
    __shared__ __nv_bfloat16 Xhi[128 * RS];
    __shared__ __nv_bfloat16 Xlo[128 * RS];
    __shared__ __nv_bfloat16 Whi[128 * RS];
    __shared__ __nv_bfloat16 Wlo[128 * RS];

    const int tid  = threadIdx.x;
    const int warp = tid >> 5;
    const int lane = tid & 31;
    const int wm   = warp >> 1;
    const int wn   = warp & 1;
    const int m0   = blockIdx.x * 128;
    const int gr   = lane >> 2;
    const int gc   = lane & 3;
    const int l16  = lane & 15;
    const int kh   = (lane >> 4) << 3;

    float c[2][8][4];
#pragma unroll
    for (int i = 0; i < 2; i++)
#pragma unroll
        for (int j = 0; j < 8; j++)
#pragma unroll
            for (int t = 0; t < 4; t++) c[i][j][t] = 0.f;

    const uint32_t xhi_b = (uint32_t)__cvta_generic_to_shared(Xhi);
    const uint32_t xlo_b = (uint32_t)__cvta_generic_to_shared(Xlo);
    const uint32_t whi_b = (uint32_t)__cvta_generic_to_shared(Whi);
    const uint32_t wlo_b = (uint32_t)__cvta_generic_to_shared(Wlo);

    float4 px[4], pw[4];
#pragma unroll
    for (int i = 0; i < 4; i++) {
        const int q   = tid + i * 256;
        const int row = q >> 3;
        const int cq  = q & 7;
        px[i] = *(const float4*)(X + (size_t)(m0 + row) * DD + cq * 4);
        pw[i] = *(const float4*)(W + (size_t)row * DD + cq * 4);
    }

    for (int kcs = 0; kcs < DD / BK; kcs++) {
#pragma unroll
        for (int i = 0; i < 4; i++) {
            const int q   = tid + i * 256;
            const int row = q >> 3;
            const int cq  = q & 7;
            {
                const float4 v = px[i];
                __nv_bfloat16 hx = __float2bfloat16(v.x);
                __nv_bfloat16 hy = __float2bfloat16(v.y);
                __nv_bfloat16 hz = __float2bfloat16(v.z);
                __nv_bfloat16 hw = __float2bfloat16(v.w);
                __nv_bfloat162 hp0 = __halves2bfloat162(hx, hy);
                __nv_bfloat162 hp1 = __halves2bfloat162(hz, hw);
                __nv_bfloat162 lp0 = __halves2bfloat162(
                    __float2bfloat16(v.x - __bfloat162float(hx)),
                    __float2bfloat16(v.y - __bfloat162float(hy)));
                __nv_bfloat162 lp1 = __halves2bfloat162(
                    __float2bfloat16(v.z - __bfloat162float(hz)),
                    __float2bfloat16(v.w - __bfloat162float(hw)));
                *(uint2*)&Xhi[row * RS + cq * 4] =
                    make_uint2(*(uint32_t*)&hp0, *(uint32_t*)&hp1);
                *(uint2*)&Xlo[row * RS + cq * 4] =
                    make_uint2(*(uint32_t*)&lp0, *(uint32_t*)&lp1);
            }
            {
                const float4 v = pw[i];
                __nv_bfloat16 hx = __float2bfloat16(v.x);
                __nv_bfloat16 hy = __float2bfloat16(v.y);
                __nv_bfloat16 hz = __float2bfloat16(v.z);
                __nv_bfloat16 hw = __float2bfloat16(v.w);
                __nv_bfloat162 hp0 = __halves2bfloat162(hx, hy);
                __nv_bfloat162 hp1 = __halves2bfloat162(hz, hw);
                __nv_bfloat162 lp0 = __halves2bfloat162(
                    __float2bfloat16(v.x - __bfloat162float(hx)),
                    __float2bfloat16(v.y - __bfloat162float(hy)));
                __nv_bfloat162 lp1 = __halves2bfloat162(
                    __float2bfloat16(v.z - __bfloat162float(hz)),
                    __float2bfloat16(v.w - __bfloat162float(hw)));
                *(uint2*)&Whi[row * RS + cq * 4] =
                    make_uint2(*(uint32_t*)&hp0, *(uint32_t*)&hp1);
                *(uint2*)&Wlo[row * RS + cq * 4] =
                    make_uint2(*(uint32_t*)&lp0, *(uint32_t*)&lp1);
            }
        }
        __syncthreads();

        if (kcs + 1 < DD / BK) {
            const int kc = (kcs + 1) * BK;
#pragma unroll
            for (int i = 0; i < 4; i++) {
                const int q   = tid + i * 256;
                const int row = q >> 3;
                const int cq  = q & 7;
                px[i] = *(const float4*)(X + (size_t)(m0 + row) * DD + kc + cq * 4);
                pw[i] = *(const float4*)(W + (size_t)row * DD + kc + cq * 4);
            }
        }

#pragma unroll
        for (int s = 0; s < BK / 16; s++) {
            const uint32_t koff = (kh + s * 16) * 2;

            uint32_t ahi[2][4], alo[2][4];
#pragma unroll
            for (int am = 0; am < 2; am++) {
                const uint32_t ro = (uint32_t)(wm * 32 + am * 16 + l16) * (RS * 2) + koff;
                LDSM4(ahi[am][0], ahi[am][1], ahi[am][2], ahi[am][3], xhi_b + ro);
                LDSM4(alo[am][0], alo[am][1], alo[am][2], alo[am][3], xlo_b + ro);
            }
            uint32_t bhi[4][4], blo[4][4];
#pragma unroll
            for (int p = 0; p < 4; p++) {
                const uint32_t ro = (uint32_t)(wn * 64 + p * 16 + l16) * (RS * 2) + koff;
                LDSM4(bhi[p][0], bhi[p][1], bhi[p][2], bhi[p][3], whi_b + ro);
                LDSM4(blo[p][0], blo[p][1], blo[p][2], blo[p][3], wlo_b + ro);
            }

#pragma unroll
            for (int p = 0; p < 4; p++)
#pragma unroll
                for (int e = 0; e < 2; e++) {
                    const int an = 2 * p + e;
                    const uint32_t bh0 = bhi[p][e], bh1 = bhi[p][2 + e];
                    const uint32_t bl0 = blo[p][e], bl1 = blo[p][2 + e];
#pragma unroll
                    for (int am = 0; am < 2; am++) {
                        mma_bf16(c[am][an], ahi[am][0], ahi[am][1], ahi[am][2], ahi[am][3], bh0, bh1);
                        mma_bf16(c[am][an], ahi[am][0], ahi[am][1], ahi[am][2], ahi[am][3], bl0, bl1);
                        mma_bf16(c[am][an], alo[am][0], alo[am][1], alo[am][2], alo[am][3], bh0, bh1);
                    }
                }
        }
        __syncthreads();
    }

#pragma unroll
    for (int am = 0; am < 2; am++) {
        const int row = m0 + wm * 32 + am * 16 + gr;
#pragma unroll
        for (int an = 0; an < 8; an++) {
            const int col = wn * 64 + an * 8 + 2 * gc;
            *(__half2*)(H + (size_t)row * DD + col) =
                __floats2half2_rn(c[am][an][0], c[am][an][1]);
            *(__half2*)(H + (size_t)(row + 8) * DD + col) =
                __floats2half2_rn(c[am][an][2], c[am][an][3]);
        }
    }
}

// ---------------- kernel 2: gather + encoding + max + stats partials ------
__global__ void __launch_bounds__(256) gather_kernel(const __half* __restrict__ H,
                                                     const float* __restrict__ xyz,
                                                     const int* __restrict__ knn,
                                                     const float* __restrict__ coor,
                                                     const float* __restrict__ scale,
                                                     float* __restrict__ agg) {
    __shared__ float sh_s[8][132];
    __shared__ float sh_q[8][132];

    const int warp = (blockIdx.x * blockDim.x + threadIdx.x) >> 5;
    const int wloc = threadIdx.x >> 5;
    const int lane = threadIdx.x & 31;

    const int b = warp >> 13;
    const int base = b << 13;

    const float wx = coor[3 * lane + 0];
    const float wy = coor[3 * lane + 1];
    const float wz = coor[3 * lane + 2];
    const float sv = scale[lane];
    const float ws = sv * sv;

    const float* cptr = xyz + (size_t)warp * 3;
    const float cx = cptr[0], cy = cptr[1], cz = cptr[2];

    const int nb = knn[(size_t)warp * KK + (lane & 15)];

    float4 acc = make_float4(-3.402823466e38f, -3.402823466e38f,
                             -3.402823466e38f, -3.402823466e38f);

#pragma unroll
    for (int k = 0; k < KK; k++) {
        const int idx = __shfl_sync(0xffffffffu, nb, k);
        const int row = base + idx;
        const float* nx = xyz + (size_t)row * 3;
        const float rx = nx[0] - cx;
        const float ry = nx[1] - cy;
        const float rz = nx[2] - cz;
        const float r2 = fmaf(rx, rx, fmaf(ry, ry, rz * rz));
        const float e  = fmaf(rx, wx, fmaf(ry, wy, fmaf(rz, wz, r2 * ws)));
        const uint2 hv = *(const uint2*)(H + (size_t)row * DD + lane * 4);
        const float2 f0 = __half22float2(*(const __half2*)&hv.x);
        const float2 f1 = __half22float2(*(const __half2*)&hv.y);
        acc.x = fmaxf(acc.x, f0.x + e);
        acc.y = fmaxf(acc.y, f0.y + e);
        acc.z = fmaxf(acc.z, f1.x + e);
        acc.w = fmaxf(acc.w, f1.y + e);
    }

    *(float4*)(agg + (size_t)warp * DD + lane * 4) = acc;

    sh_s[wloc][lane * 4 + 0] = acc.x;
    sh_s[wloc][lane * 4 + 1] = acc.y;
    sh_s[wloc][lane * 4 + 2] = acc.z;
    sh_s[wloc][lane * 4 + 3] = acc.w;
    sh_q[wloc][lane * 4 + 0] = acc.x * acc.x;
    sh_q[wloc][lane * 4 + 1] = acc.y * acc.y;
    sh_q[wloc][lane * 4 + 2] = acc.z * acc.z;
    sh_q[wloc][lane * 4 + 3] = acc.w * acc.w;
    __syncthreads();

    if (threadIdx.x < 128) {
        const int ch = threadIdx.x;
        float s = 0.f;
#pragma unroll
        for (int w = 0; w < 8; w++) s += sh_s[w][ch];
        g_psum[blockIdx.x][ch] = s;
    } else {
        const int ch = threadIdx.x - 128;
        float q = 0.f;
#pragma unroll
        for (int w = 0; w < 8; w++) q += sh_q[w][ch];
        g_psum2[blockIdx.x][ch] = q;
    }
}

// ---------------- kernel 3a: stats stage A (coalesced) --------------------
// 128 blocks x 256 thr. Block b reduces partial-rows [32b, 32b+32).
// Thread (c = tid&127, j = tid>>7): warp lanes hit consecutive channels.
__global__ void __launch_bounds__(256) statsA_kernel() {
    __shared__ float sh[256], sh2[256];
    const int c = threadIdx.x & 127;
    const int j = threadIdx.x >> 7;        // 0,1
    const int p0 = blockIdx.x * 32;

    float s = 0.f, q = 0.f;
#pragma unroll
    for (int i = 0; i < 16; i++) {
        const int p = p0 + j + 2 * i;
        s += g_psum[p][c];
        q += g_psum2[p][c];
    }
    sh[threadIdx.x]  = s;
    sh2[threadIdx.x] = q;
    __syncthreads();
    if (j == 0) {
        g_mid [blockIdx.x][c] = sh[c]  + sh[c + 128];
        g_mid2[blockIdx.x][c] = sh2[c] + sh2[c + 128];
    }
}

// ---------------- kernel 3b: stats stage B + scale/shift ------------------
// 1 block x 1024 thr. Thread (c = tid&127, j = tid>>7 in 0..7).
__global__ void __launch_bounds__(1024) statsB_kernel(const float* __restrict__ bn_w,
                                                      const float* __restrict__ bn_b) {
    __shared__ float sh[8][DD], sh2[8][DD];
    const int c = threadIdx.x & 127;
    const int j = threadIdx.x >> 7;        // 0..7

    float s = 0.f, q = 0.f;
#pragma unroll
    for (int i = 0; i < 16; i++) {
        const int p = j + 8 * i;
        s += g_mid[p][c];
        q += g_mid2[p][c];
    }
    sh[j][c]  = s;
    sh2[j][c] = q;
    __syncthreads();

    if (j == 0) {
        float ts = 0.f, tq = 0.f;
#pragma unroll
        for (int w = 0; w < 8; w++) {
            ts += sh[w][c];
            tq += sh2[w][c];
        }
        const float inv_m = 1.f / (float)MM;
        const float mean = ts * inv_m;
        const float var  = fmaf(-mean, mean, tq * inv_m);
        const float a = bn_w[c] * rsqrtf(var + BN_EPS);
        g_scale[c] = a;
        g_shift[c] = fmaf(-mean, a, bn_b[c]);
    }
}

// ---------------- kernel 4: in-place normalize (register LUT) -------------
__global__ void __launch_bounds__(256) norm_kernel(float* __restrict__ out) {
    const int t0 = blockIdx.x * blockDim.x + threadIdx.x;
    const int c0 = (t0 & 31) * 4;
    const float s0 = g_scale[c0 + 0], s1 = g_scale[c0 + 1];
    const float s2 = g_scale[c0 + 2], s3 = g_scale[c0 + 3];
    const float b0 = g_shift[c0 + 0], b1 = g_shift[c0 + 1];
    const float b2 = g_shift[c0 + 2], b3 = g_shift[c0 + 3];

    const int total  = MM * (DD / 4);
    const int stride = gridDim.x * blockDim.x;   // multiple of 32

    for (int t = t0; t < total; t += stride) {
        float4 v = __ldcs((const float4*)out + t);
        v.x = fmaf(v.x, s0, b0);
        v.y = fmaf(v.y, s1, b1);
        v.z = fmaf(v.z, s2, b2);
        v.w = fmaf(v.w, s3, b3);
        __stcs((float4*)out + t, v);
    }
}

// ---------------- launch ---------------------------------------------------
extern "C" void kernel_launch(void* const* d_in, const int* in_sizes, int n_in,
                              void* d_out, int out_size) {
    const float* x      = (const float*)d_in[0];
    const float* xyz    = (const float*)d_in[1];
    const int*   knn    = (const int*)  d_in[2];
    const float* proj_w = (const float*)d_in[3];
    const float* coor   = (const float*)d_in[4];
    const float* scale  = (const float*)d_in[5];
    const float* bn_w   = (const float*)d_in[6];
    const float* bn_b   = (const float*)d_in[7];
    float* out = (float*)d_out;

    __half* h;
    cudaGetSymbolAddress((void**)&h, g_h);

    gemm_kernel<<<MM / 128, 256>>>(x, proj_w, h);
    gather_kernel<<<MM / 8, 256>>>(h, xyz, knn, coor, scale, out);
    statsA_kernel<<<128, 256>>>();
    statsB_kernel<<<1, 1024>>>(bn_w, bn_b);
    norm_kernel<<<1024, 256>>>(out);
}

// round 10
// speedup vs baseline: 1.2525x; 1.1206x over previous
#include <cuda_runtime.h>
#include <cuda_fp16.h>
#include <cstdint>

#define BB 4
#define NN 8192
#define KK 16
#define DD 128
#define GG 32
#define MM (BB*NN)          // 32768 rows
#define BN_EPS 1e-5f

#define NPART 4096          // gather blocks = stats partials
#define NMID 32             // stats stage-A output rows

// ---------------- scratch (device globals; no allocation) ----------------
__device__ __half g_h[(size_t)MM * DD];       // projected features, fp16, 8 MB
__device__ float g_psum [NPART][DD];          // per-gather-block partial sums
__device__ float g_psum2[NPART][DD];          // per-gather-block partial sumsq
__device__ float g_mid  [NMID][DD];           // stage-A sums
__device__ float g_mid2 [NMID][DD];           // stage-A sumsq

// ---------------- mma / ldmatrix helpers ----------------------------------
#define LDSM4(r0, r1, r2, r3, addr)                                            \
    asm volatile("ldmatrix.sync.aligned.m8n8.x4.shared.b16 {%0,%1,%2,%3}, [%4];" \
                 : "=r"(r0), "=r"(r1), "=r"(r2), "=r"(r3) : "r"(addr))

__device__ __forceinline__ void mma_f16(float c[4],
                                        uint32_t a0, uint32_t a1, uint32_t a2, uint32_t a3,
                                        uint32_t b0, uint32_t b1) {
    asm volatile(
        "mma.sync.aligned.m16n8k16.row.col.f32.f16.f16.f32 "
        "{%0,%1,%2,%3}, {%4,%5,%6,%7}, {%8,%9}, {%0,%1,%2,%3};"
        : "+f"(c[0]), "+f"(c[1]), "+f"(c[2]), "+f"(c[3])
        : "r"(a0), "r"(a1), "r"(a2), "r"(a3), "r"(b0), "r"(b1));
}

// ---------------- kernel 1: H = X * W^T, single-term fp16 HMMA ------------
// Block 256 thr (8 warps: wm 0..3, wn 0..1). Tile M128 x N128, warp 32x64.
// K staged by 32 (2 k16 MMA steps per stage); global prefetch registers.
#define BK 32
#define RS 40   // smem row stride in fp16 elems (80 B -> LDSM conflict-free)
__global__ void __launch_bounds__(256) gemm_kernel(const float* __restrict__ X,
                                                   const float* __restrict__ W,
                                                   __half* __restrict__ H) {
    __shared__ __half Xs[128 * RS];
    __shared__ __half Ws[128 * RS];

    const int tid  = threadIdx.x;
    const int warp = tid >> 5;
    const int lane = tid & 31;
    const int wm   = warp >> 1;          // M offset wm*32
    const int wn   = warp & 1;           // N offset wn*64
    const int m0   = blockIdx.x * 128;
    const int gr   = lane >> 2;
    const int gc   = lane & 3;
    const int l16  = lane & 15;
    const int kh   = (lane >> 4) << 3;

    float c[2][8][4];
#pragma unroll
    for (int i = 0; i < 2; i++)
#pragma unroll
        for (int j = 0; j < 8; j++)
#pragma unroll
            for (int t = 0; t < 4; t++) c[i][j][t] = 0.f;

    const uint32_t xs_b = (uint32_t)__cvta_generic_to_shared(Xs);
    const uint32_t ws_b = (uint32_t)__cvta_generic_to_shared(Ws);

    float4 px[4], pw[4];
#pragma unroll
    for (int i = 0; i < 4; i++) {
        const int q   = tid + i * 256;
        const int row = q >> 3;
        const int cq  = q & 7;
        px[i] = *(const float4*)(X + (size_t)(m0 + row) * DD + cq * 4);
        pw[i] = *(const float4*)(W + (size_t)row * DD + cq * 4);
    }

    for (int kcs = 0; kcs < DD / BK; kcs++) {
        // convert + store current stage
#pragma unroll
        for (int i = 0; i < 4; i++) {
            const int q   = tid + i * 256;
            const int row = q >> 3;
            const int cq  = q & 7;
            {
                const float4 v = px[i];
                const __half2 p0 = __floats2half2_rn(v.x, v.y);
                const __half2 p1 = __floats2half2_rn(v.z, v.w);
                *(uint2*)&Xs[row * RS + cq * 4] =
                    make_uint2(*(const uint32_t*)&p0, *(const uint32_t*)&p1);
            }
            {
                const float4 v = pw[i];
                const __half2 p0 = __floats2half2_rn(v.x, v.y);
                const __half2 p1 = __floats2half2_rn(v.z, v.w);
                *(uint2*)&Ws[row * RS + cq * 4] =
                    make_uint2(*(const uint32_t*)&p0, *(const uint32_t*)&p1);
            }
        }
        __syncthreads();

        // prefetch next stage
        if (kcs + 1 < DD / BK) {
            const int kc = (kcs + 1) * BK;
#pragma unroll
            for (int i = 0; i < 4; i++) {
                const int q   = tid + i * 256;
                const int row = q >> 3;
                const int cq  = q & 7;
                px[i] = *(const float4*)(X + (size_t)(m0 + row) * DD + kc + cq * 4);
                pw[i] = *(const float4*)(W + (size_t)row * DD + kc + cq * 4);
            }
        }

#pragma unroll
        for (int s = 0; s < BK / 16; s++) {
            const uint32_t koff = (kh + s * 16) * 2;   // byte offset of k half

            uint32_t a[2][4];
#pragma unroll
            for (int am = 0; am < 2; am++) {
                const uint32_t ro = (uint32_t)(wm * 32 + am * 16 + l16) * (RS * 2) + koff;
                LDSM4(a[am][0], a[am][1], a[am][2], a[am][3], xs_b + ro);
            }
            uint32_t bb[4][4];   // [pair][b0_even, b0_odd, b1_even, b1_odd]
#pragma unroll
            for (int p = 0; p < 4; p++) {
                const uint32_t ro = (uint32_t)(wn * 64 + p * 16 + l16) * (RS * 2) + koff;
                LDSM4(bb[p][0], bb[p][1], bb[p][2], bb[p][3], ws_b + ro);
            }

#pragma unroll
            for (int p = 0; p < 4; p++)
#pragma unroll
                for (int e = 0; e < 2; e++) {
                    const int an = 2 * p + e;
#pragma unroll
                    for (int am = 0; am < 2; am++)
                        mma_f16(c[am][an], a[am][0], a[am][1], a[am][2], a[am][3],
                                bb[p][e], bb[p][2 + e]);
                }
        }
        __syncthreads();
    }

    // epilogue -> fp16 H (R4 form)
#pragma unroll
    for (int am = 0; am < 2; am++) {
        const int row = m0 + wm * 32 + am * 16 + gr;
#pragma unroll
        for (int an = 0; an < 8; an++) {
            const int col = wn * 64 + an * 8 + 2 * gc;
            *(__half2*)(H + (size_t)row * DD + col) =
                __floats2half2_rn(c[am][an][0], c[am][an][1]);
            *(__half2*)(H + (size_t)(row + 8) * DD + col) =
                __floats2half2_rn(c[am][an][2], c[am][an][3]);
        }
    }
}

// ---------------- kernel 2: gather + encoding + max + stats partials ------
__global__ void __launch_bounds__(256) gather_kernel(const __half* __restrict__ H,
                                                     const float* __restrict__ xyz,
                                                     const int* __restrict__ knn,
                                                     const float* __restrict__ coor,
                                                     const float* __restrict__ scale,
                                                     float* __restrict__ agg) {
    __shared__ float sh_s[8][132];
    __shared__ float sh_q[8][132];

    const int warp = (blockIdx.x * blockDim.x + threadIdx.x) >> 5;
    const int wloc = threadIdx.x >> 5;
    const int lane = threadIdx.x & 31;

    const int b = warp >> 13;
    const int base = b << 13;

    const float wx = coor[3 * lane + 0];
    const float wy = coor[3 * lane + 1];
    const float wz = coor[3 * lane + 2];
    const float sv = scale[lane];
    const float ws = sv * sv;

    const float* cptr = xyz + (size_t)warp * 3;
    const float cx = cptr[0], cy = cptr[1], cz = cptr[2];

    const int nb = knn[(size_t)warp * KK + (lane & 15)];

    float4 acc = make_float4(-3.402823466e38f, -3.402823466e38f,
                             -3.402823466e38f, -3.402823466e38f);

#pragma unroll
    for (int k = 0; k < KK; k++) {
        const int idx = __shfl_sync(0xffffffffu, nb, k);
        const int row = base + idx;
        const float* nx = xyz + (size_t)row * 3;
        const float rx = nx[0] - cx;
        const float ry = nx[1] - cy;
        const float rz = nx[2] - cz;
        const float r2 = fmaf(rx, rx, fmaf(ry, ry, rz * rz));
        const float e  = fmaf(rx, wx, fmaf(ry, wy, fmaf(rz, wz, r2 * ws)));
        const uint2 hv = *(const uint2*)(H + (size_t)row * DD + lane * 4);
        const float2 f0 = __half22float2(*(const __half2*)&hv.x);
        const float2 f1 = __half22float2(*(const __half2*)&hv.y);
        acc.x = fmaxf(acc.x, f0.x + e);
        acc.y = fmaxf(acc.y, f0.y + e);
        acc.z = fmaxf(acc.z, f1.x + e);
        acc.w = fmaxf(acc.w, f1.y + e);
    }

    *(float4*)(agg + (size_t)warp * DD + lane * 4) = acc;

    sh_s[wloc][lane * 4 + 0] = acc.x;
    sh_s[wloc][lane * 4 + 1] = acc.y;
    sh_s[wloc][lane * 4 + 2] = acc.z;
    sh_s[wloc][lane * 4 + 3] = acc.w;
    sh_q[wloc][lane * 4 + 0] = acc.x * acc.x;
    sh_q[wloc][lane * 4 + 1] = acc.y * acc.y;
    sh_q[wloc][lane * 4 + 2] = acc.z * acc.z;
    sh_q[wloc][lane * 4 + 3] = acc.w * acc.w;
    __syncthreads();

    if (threadIdx.x < 128) {
        const int ch = threadIdx.x;
        float s = 0.f;
#pragma unroll
        for (int w = 0; w < 8; w++) s += sh_s[w][ch];
        g_psum[blockIdx.x][ch] = s;
    } else {
        const int ch = threadIdx.x - 128;
        float q = 0.f;
#pragma unroll
        for (int w = 0; w < 8; w++) q += sh_q[w][ch];
        g_psum2[blockIdx.x][ch] = q;
    }
}

// ---------------- kernel 3: stats stage A (coalesced, 4096 -> 32 rows) ----
// 32 blocks x 256 thr. Block b reduces partial-rows [128b, 128b+128).
__global__ void __launch_bounds__(256) statsA_kernel() {
    __shared__ float sh[256], sh2[256];
    const int c = threadIdx.x & 127;
    const int j = threadIdx.x >> 7;        // 0,1
    const int p0 = blockIdx.x * 128;

    float s = 0.f, q = 0.f;
#pragma unroll 8
    for (int i = 0; i < 64; i++) {
        const int p = p0 + j + 2 * i;
        s += g_psum[p][c];
        q += g_psum2[p][c];
    }
    sh[threadIdx.x]  = s;
    sh2[threadIdx.x] = q;
    __syncthreads();
    if (j == 0) {
        g_mid [blockIdx.x][c] = sh[c]  + sh[c + 128];
        g_mid2[blockIdx.x][c] = sh2[c] + sh2[c + 128];
    }
}

// ---------------- kernel 4: finalize stats (per-block) + normalize --------
// 256 blocks; each block redundantly reduces g_mid (32x128, 16 KB L2-hot),
// computes scale/shift, then normalizes its slice of out in place.
__global__ void __launch_bounds__(256) norm_kernel(float* __restrict__ out,
                                                   const float* __restrict__ bn_w,
                                                   const float* __restrict__ bn_b) {
    __shared__ float sh[2][DD], sh2[2][DD], sa[DD], sb[DD];
    const int c = threadIdx.x & 127;
    const int j = threadIdx.x >> 7;

    float s = 0.f, q = 0.f;
#pragma unroll
    for (int i = 0; i < 16; i++) {
        const int p = j + 2 * i;
        s += g_mid[p][c];
        q += g_mid2[p][c];
    }
    sh[j][c]  = s;
    sh2[j][c] = q;
    __syncthreads();
    if (j == 0) {
        const float ts = sh[0][c] + sh[1][c];
        const float tq = sh2[0][c] + sh2[1][c];
        const float inv_m = 1.f / (float)MM;
        const float mean = ts * inv_m;
        const float var  = fmaf(-mean, mean, tq * inv_m);
        const float a = bn_w[c] * rsqrtf(var + BN_EPS);
        sa[c] = a;
        sb[c] = fmaf(-mean, a, bn_b[c]);
    }
    __syncthreads();

    const int t0 = blockIdx.x * blockDim.x + threadIdx.x;
    const int c0 = (t0 & 31) * 4;
    const float s0 = sa[c0 + 0], s1 = sa[c0 + 1], s2 = sa[c0 + 2], s3 = sa[c0 + 3];
    const float b0 = sb[c0 + 0], b1 = sb[c0 + 1], b2 = sb[c0 + 2], b3 = sb[c0 + 3];

    const int total  = MM * (DD / 4);
    const int stride = 256 * 256;     // multiple of 32

    for (int t = t0; t < total; t += stride) {
        float4 v = __ldcs((const float4*)out + t);
        v.x = fmaf(v.x, s0, b0);
        v.y = fmaf(v.y, s1, b1);
        v.z = fmaf(v.z, s2, b2);
        v.w = fmaf(v.w, s3, b3);
        __stcs((float4*)out + t, v);
    }
}

// ---------------- launch ---------------------------------------------------
extern "C" void kernel_launch(void* const* d_in, const int* in_sizes, int n_in,
                              void* d_out, int out_size) {
    const float* x      = (const float*)d_in[0];
    const float* xyz    = (const float*)d_in[1];
    const int*   knn    = (const int*)  d_in[2];
    const float* proj_w = (const float*)d_in[3];
    const float* coor   = (const float*)d_in[4];
    const float* scale  = (const float*)d_in[5];
    const float* bn_w   = (const float*)d_in[6];
    const float* bn_b   = (const float*)d_in[7];
    float* out = (float*)d_out;

    __half* h;
    cudaGetSymbolAddress((void**)&h, g_h);

    gemm_kernel<<<MM / 128, 256>>>(x, proj_w, h);
    gather_kernel<<<MM / 8, 256>>>(h, xyz, knn, coor, scale, out);
    statsA_kernel<<<32, 256>>>();
    norm_kernel<<<256, 256>>>(out, bn_w, bn_b);
}

// round 11
// speedup vs baseline: 1.4223x; 1.1356x over previous
#include <cuda_runtime.h>
#include <cuda_fp16.h>
#include <cstdint>

#define BB 4
#define NN 8192
#define KK 16
#define DD 128
#define GG 32
#define MM (BB*NN)          // 32768 rows
#define BN_EPS 1e-5f

#define NPART 2048          // gather blocks (16 points each) = stats partials
#define NMID 32             // stats stage-A output rows

// ---------------- scratch (device globals; no allocation) ----------------
__device__ __half g_h[(size_t)MM * DD];       // projected features, fp16, 8 MB
__device__ float g_psum [NPART][DD];
__device__ float g_psum2[NPART][DD];
__device__ float g_mid  [NMID][DD];
__device__ float g_mid2 [NMID][DD];

// ---------------- mma / ldmatrix helpers ----------------------------------
#define LDSM4(r0, r1, r2, r3, addr)                                            \
    asm volatile("ldmatrix.sync.aligned.m8n8.x4.shared.b16 {%0,%1,%2,%3}, [%4];" \
                 : "=r"(r0), "=r"(r1), "=r"(r2), "=r"(r3) : "r"(addr))

__device__ __forceinline__ void mma_f16(float c[4],
                                        uint32_t a0, uint32_t a1, uint32_t a2, uint32_t a3,
                                        uint32_t b0, uint32_t b1) {
    asm volatile(
        "mma.sync.aligned.m16n8k16.row.col.f32.f16.f16.f32 "
        "{%0,%1,%2,%3}, {%4,%5,%6,%7}, {%8,%9}, {%0,%1,%2,%3};"
        : "+f"(c[0]), "+f"(c[1]), "+f"(c[2]), "+f"(c[3])
        : "r"(a0), "r"(a1), "r"(a2), "r"(a3), "r"(b0), "r"(b1));
}

// ---------------- kernel 1: H = X * W^T, single-term fp16 HMMA ------------
#define BK 32
#define RS 40   // smem row stride in fp16 elems (80 B -> LDSM conflict-free)
__global__ void __launch_bounds__(256) gemm_kernel(const float* __restrict__ X,
                                                   const float* __restrict__ W,
                                                   __half* __restrict__ H) {
    __shared__ __half Xs[128 * RS];
    __shared__ __half Ws[128 * RS];

    const int tid  = threadIdx.x;
    const int warp = tid >> 5;
    const int lane = tid & 31;
    const int wm   = warp >> 1;
    const int wn   = warp & 1;
    const int m0   = blockIdx.x * 128;
    const int gr   = lane >> 2;
    const int gc   = lane & 3;
    const int l16  = lane & 15;
    const int kh   = (lane >> 4) << 3;

    float c[2][8][4];
#pragma unroll
    for (int i = 0; i < 2; i++)
#pragma unroll
        for (int j = 0; j < 8; j++)
#pragma unroll
            for (int t = 0; t < 4; t++) c[i][j][t] = 0.f;

    const uint32_t xs_b = (uint32_t)__cvta_generic_to_shared(Xs);
    const uint32_t ws_b = (uint32_t)__cvta_generic_to_shared(Ws);

    float4 px[4], pw[4];
#pragma unroll
    for (int i = 0; i < 4; i++) {
        const int q   = tid + i * 256;
        const int row = q >> 3;
        const int cq  = q & 7;
        px[i] = *(const float4*)(X + (size_t)(m0 + row) * DD + cq * 4);
        pw[i] = *(const float4*)(W + (size_t)row * DD + cq * 4);
    }

    for (int kcs = 0; kcs < DD / BK; kcs++) {
#pragma unroll
        for (int i = 0; i < 4; i++) {
            const int q   = tid + i * 256;
            const int row = q >> 3;
            const int cq  = q & 7;
            {
                const float4 v = px[i];
                const __half2 p0 = __floats2half2_rn(v.x, v.y);
                const __half2 p1 = __floats2half2_rn(v.z, v.w);
                *(uint2*)&Xs[row * RS + cq * 4] =
                    make_uint2(*(const uint32_t*)&p0, *(const uint32_t*)&p1);
            }
            {
                const float4 v = pw[i];
                const __half2 p0 = __floats2half2_rn(v.x, v.y);
                const __half2 p1 = __floats2half2_rn(v.z, v.w);
                *(uint2*)&Ws[row * RS + cq * 4] =
                    make_uint2(*(const uint32_t*)&p0, *(const uint32_t*)&p1);
            }
        }
        __syncthreads();

        if (kcs + 1 < DD / BK) {
            const int kc = (kcs + 1) * BK;
#pragma unroll
            for (int i = 0; i < 4; i++) {
                const int q   = tid + i * 256;
                const int row = q >> 3;
                const int cq  = q & 7;
                px[i] = *(const float4*)(X + (size_t)(m0 + row) * DD + kc + cq * 4);
                pw[i] = *(const float4*)(W + (size_t)row * DD + kc + cq * 4);
            }
        }

#pragma unroll
        for (int s = 0; s < BK / 16; s++) {
            const uint32_t koff = (kh + s * 16) * 2;

            uint32_t a[2][4];
#pragma unroll
            for (int am = 0; am < 2; am++) {
                const uint32_t ro = (uint32_t)(wm * 32 + am * 16 + l16) * (RS * 2) + koff;
                LDSM4(a[am][0], a[am][1], a[am][2], a[am][3], xs_b + ro);
            }
            uint32_t bb[4][4];
#pragma unroll
            for (int p = 0; p < 4; p++) {
                const uint32_t ro = (uint32_t)(wn * 64 + p * 16 + l16) * (RS * 2) + koff;
                LDSM4(bb[p][0], bb[p][1], bb[p][2], bb[p][3], ws_b + ro);
            }

#pragma unroll
            for (int p = 0; p < 4; p++)
#pragma unroll
                for (int e = 0; e < 2; e++) {
                    const int an = 2 * p + e;
#pragma unroll
                    for (int am = 0; am < 2; am++)
                        mma_f16(c[am][an], a[am][0], a[am][1], a[am][2], a[am][3],
                                bb[p][e], bb[p][2 + e]);
                }
        }
        __syncthreads();
    }

#pragma unroll
    for (int am = 0; am < 2; am++) {
        const int row = m0 + wm * 32 + am * 16 + gr;
#pragma unroll
        for (int an = 0; an < 8; an++) {
            const int col = wn * 64 + an * 8 + 2 * gc;
            *(__half2*)(H + (size_t)row * DD + col) =
                __floats2half2_rn(c[am][an][0], c[am][an][1]);
            *(__half2*)(H + (size_t)(row + 8) * DD + col) =
                __floats2half2_rn(c[am][an][2], c[am][an][3]);
        }
    }
}

// ---------------- kernel 2: gather, 2 points/warp, uint4 loads ------------
// Warp handles points p0 (lanes 0-15) and p0+1 (lanes 16-31). Lane (half,l16)
// owns 8 channels [l16*8, l16*8+8). One LDG.128 per k serves both points.
__global__ void __launch_bounds__(256) gather_kernel(const __half* __restrict__ H,
                                                     const float* __restrict__ xyz,
                                                     const int* __restrict__ knn,
                                                     const float* __restrict__ coor,
                                                     const float* __restrict__ scale,
                                                     float* __restrict__ agg) {
    __shared__ float sh_s[16][132];
    __shared__ float sh_q[16][132];

    const int tid   = threadIdx.x;
    const int wloc  = tid >> 5;
    const int lane  = tid & 31;
    const int half  = lane >> 4;
    const int l16   = lane & 15;
    const int point = blockIdx.x * 16 + wloc * 2 + half;

    const int b = point >> 13;
    const int base = b << 13;

    // encoding weights for the lane's 2 groups (g0 = 2*l16, g1 = 2*l16+1)
    const int g0 = 2 * l16, g1 = 2 * l16 + 1;
    const float wx0 = coor[3 * g0 + 0], wy0 = coor[3 * g0 + 1], wz0 = coor[3 * g0 + 2];
    const float wx1 = coor[3 * g1 + 0], wy1 = coor[3 * g1 + 1], wz1 = coor[3 * g1 + 2];
    const float sv0 = scale[g0], sv1 = scale[g1];
    const float ws0 = sv0 * sv0, ws1 = sv1 * sv1;

    const float* cptr = xyz + (size_t)point * 3;
    const float cx = cptr[0], cy = cptr[1], cz = cptr[2];

    // lane l16 of each half holds its point's l16-th neighbor
    const int nb = knn[(size_t)point * KK + l16];
    const float* nxp = xyz + (size_t)(base + nb) * 3;
    const float rxl = nxp[0] - cx;
    const float ryl = nxp[1] - cy;
    const float rzl = nxp[2] - cz;
    const float r2l = fmaf(rxl, rxl, fmaf(ryl, ryl, rzl * rzl));

    const float NEG = -3.402823466e38f;
    float acc[8] = {NEG, NEG, NEG, NEG, NEG, NEG, NEG, NEG};

    const __half* hbase = H + (size_t)base * DD + l16 * 8;

#pragma unroll
    for (int k = 0; k < KK; k++) {
        // width-16 segmented shuffles: each half gets its own point's values
        const int   idx = __shfl_sync(0xffffffffu, nb,  k, 16);
        const float rx  = __shfl_sync(0xffffffffu, rxl, k, 16);
        const float ry  = __shfl_sync(0xffffffffu, ryl, k, 16);
        const float rz  = __shfl_sync(0xffffffffu, rzl, k, 16);
        const float r2  = __shfl_sync(0xffffffffu, r2l, k, 16);
        const float e0  = fmaf(rx, wx0, fmaf(ry, wy0, fmaf(rz, wz0, r2 * ws0)));
        const float e1  = fmaf(rx, wx1, fmaf(ry, wy1, fmaf(rz, wz1, r2 * ws1)));

        const uint4 hv = *(const uint4*)(hbase + (size_t)idx * DD);
        const float2 f0 = __half22float2(*(const __half2*)&hv.x);
        const float2 f1 = __half22float2(*(const __half2*)&hv.y);
        const float2 f2 = __half22float2(*(const __half2*)&hv.z);
        const float2 f3 = __half22float2(*(const __half2*)&hv.w);
        acc[0] = fmaxf(acc[0], f0.x + e0);
        acc[1] = fmaxf(acc[1], f0.y + e0);
        acc[2] = fmaxf(acc[2], f1.x + e0);
        acc[3] = fmaxf(acc[3], f1.y + e0);
        acc[4] = fmaxf(acc[4], f2.x + e1);
        acc[5] = fmaxf(acc[5], f2.y + e1);
        acc[6] = fmaxf(acc[6], f3.x + e1);
        acc[7] = fmaxf(acc[7], f3.y + e1);
    }

    // store agg (fp32): 2 float4 per lane, coalesced within halves
    float* aout = agg + (size_t)point * DD + l16 * 8;
    *(float4*)(aout)     = make_float4(acc[0], acc[1], acc[2], acc[3]);
    *(float4*)(aout + 4) = make_float4(acc[4], acc[5], acc[6], acc[7]);

    // stats partials
    const int prow = wloc * 2 + half;
    const int cb = l16 * 8;
#pragma unroll
    for (int i = 0; i < 8; i++) {
        sh_s[prow][cb + i] = acc[i];
        sh_q[prow][cb + i] = acc[i] * acc[i];
    }
    __syncthreads();

    if (tid < 128) {
        const int ch = tid;
        float s = 0.f;
#pragma unroll
        for (int p = 0; p < 16; p++) s += sh_s[p][ch];
        g_psum[blockIdx.x][ch] = s;
    } else {
        const int ch = tid - 128;
        float q = 0.f;
#pragma unroll
        for (int p = 0; p < 16; p++) q += sh_q[p][ch];
        g_psum2[blockIdx.x][ch] = q;
    }
}

// ---------------- kernel 3: stats stage A (coalesced, 2048 -> 32 rows) ----
__global__ void __launch_bounds__(256) statsA_kernel() {
    __shared__ float sh[256], sh2[256];
    const int c = threadIdx.x & 127;
    const int j = threadIdx.x >> 7;
    const int p0 = blockIdx.x * 64;

    float s = 0.f, q = 0.f;
#pragma unroll 8
    for (int i = 0; i < 32; i++) {
        const int p = p0 + j + 2 * i;
        s += g_psum[p][c];
        q += g_psum2[p][c];
    }
    sh[threadIdx.x]  = s;
    sh2[threadIdx.x] = q;
    __syncthreads();
    if (j == 0) {
        g_mid [blockIdx.x][c] = sh[c]  + sh[c + 128];
        g_mid2[blockIdx.x][c] = sh2[c] + sh2[c + 128];
    }
}

// ---------------- kernel 4: finalize stats (per-block) + normalize --------
#define NORMG 768
__global__ void __launch_bounds__(256) norm_kernel(float* __restrict__ out,
                                                   const float* __restrict__ bn_w,
                                                   const float* __restrict__ bn_b) {
    __shared__ float sh[2][DD], sh2[2][DD], sa[DD], sb[DD];
    const int c = threadIdx.x & 127;
    const int j = threadIdx.x >> 7;

    float s = 0.f, q = 0.f;
#pragma unroll
    for (int i = 0; i < 16; i++) {
        const int p = j + 2 * i;
        s += g_mid[p][c];
        q += g_mid2[p][c];
    }
    sh[j][c]  = s;
    sh2[j][c] = q;
    __syncthreads();
    if (j == 0) {
        const float ts = sh[0][c] + sh[1][c];
        const float tq = sh2[0][c] + sh2[1][c];
        const float inv_m = 1.f / (float)MM;
        const float mean = ts * inv_m;
        const float var  = fmaf(-mean, mean, tq * inv_m);
        const float a = bn_w[c] * rsqrtf(var + BN_EPS);
        sa[c] = a;
        sb[c] = fmaf(-mean, a, bn_b[c]);
    }
    __syncthreads();

    const int t0 = blockIdx.x * blockDim.x + threadIdx.x;
    const int c0 = (t0 & 31) * 4;
    const float s0 = sa[c0 + 0], s1 = sa[c0 + 1], s2 = sa[c0 + 2], s3 = sa[c0 + 3];
    const float b0 = sb[c0 + 0], b1 = sb[c0 + 1], b2 = sb[c0 + 2], b3 = sb[c0 + 3];

    const int total  = MM * (DD / 4);
    const int stride = NORMG * 256;   // multiple of 32

    for (int t = t0; t < total; t += stride) {
        float4 v = __ldcs((const float4*)out + t);
        v.x = fmaf(v.x, s0, b0);
        v.y = fmaf(v.y, s1, b1);
        v.z = fmaf(v.z, s2, b2);
        v.w = fmaf(v.w, s3, b3);
        __stcs((float4*)out + t, v);
    }
}

// ---------------- launch ---------------------------------------------------
extern "C" void kernel_launch(void* const* d_in, const int* in_sizes, int n_in,
                              void* d_out, int out_size) {
    const float* x      = (const float*)d_in[0];
    const float* xyz    = (const float*)d_in[1];
    const int*   knn    = (const int*)  d_in[2];
    const float* proj_w = (const float*)d_in[3];
    const float* coor   = (const float*)d_in[4];
    const float* scale  = (const float*)d_in[5];
    const float* bn_w   = (const float*)d_in[6];
    const float* bn_b   = (const float*)d_in[7];
    float* out = (float*)d_out;

    __half* h;
    cudaGetSymbolAddress((void**)&h, g_h);

    gemm_kernel<<<MM / 128, 256>>>(x, proj_w, h);
    gather_kernel<<<MM / 16, 256>>>(h, xyz, knn, coor, scale, out);
    statsA_kernel<<<32, 256>>>();
    norm_kernel<<<NORMG, 256>>>(out, bn_w, bn_b);
}